// round 1
// baseline (speedup 1.0000x reference)
#include <cuda_runtime.h>
#include <math.h>

#define NB   8
#define C1   256
#define C2   256
#define CM   128
#define HH   56
#define WW   56
#define HW   3136
#define NPIX (NB*HW)      // 25088
#define GG   4
#define GC   32
#define EPSS 1e-5f
#define KCONV 2304
#define NOM  108          // 72 offsets + 36 mask logits

// scratch (device globals: allocation-free rule)
__device__ float g_h [NPIX*CM];
__device__ float g_t [NPIX*CM];
__device__ float g_v [NPIX*CM];
__device__ float g_om[NPIX*NOM];
__device__ float g_o [NPIX*CM];

__device__ __forceinline__ float siluf(float v){ return v / (1.f + expf(-v)); }

// ---------------------------------------------------------------------------
// Kernel 1: 3x3 conv (C1=256 -> CM=128) + BN + SiLU, implicit GEMM.
// M tile 64 (pixels), N tile 128 (all out channels), K=2304, BK=16.
// 128 threads, 8x8 microtile.
// ---------------------------------------------------------------------------
__global__ __launch_bounds__(128) void conv1_bn_silu(
    const float* __restrict__ x, const float* __restrict__ w,
    const float* __restrict__ bg, const float* __restrict__ bb,
    const float* __restrict__ bm, const float* __restrict__ bv)
{
    __shared__ __align__(16) float As[16*68];
    __shared__ __align__(16) float Bs[16*132];
    const int t  = threadIdx.x;
    const int m0 = blockIdx.x * 64;

    // A (im2col) load mapping: fixed pixel per thread, k varies
    const int am  = t & 63;
    const int ak0 = t >> 6;                 // 0..1, k = ak0 + 2*i
    const int mg  = m0 + am;
    const int img = mg / HW;
    const int p   = mg - img*HW;
    const int py  = p / WW;
    const int px  = p - py*WW;
    const float* xb = x + (size_t)img * C1 * HW;

    // B load mapping: k fixed = t&15, o = t>>4 + 8*i
    const int bk  = t & 15;
    const int bo0 = t >> 4;

    const int tx = t & 15, ty = t >> 4;
    float acc[8][8];
    #pragma unroll
    for (int r = 0; r < 8; r++)
        #pragma unroll
        for (int c = 0; c < 8; c++) acc[r][c] = 0.f;

    for (int kb = 0; kb < KCONV; kb += 16) {
        #pragma unroll
        for (int i = 0; i < 8; i++) {
            int k  = ak0 + i*2;
            int kg = kb + k;
            int c  = kg / 9;
            int r9 = kg - c*9;
            int ky = r9 / 3;
            int kx = r9 - ky*3;
            int yy = py + ky - 1;
            int xx = px + kx - 1;
            float v = 0.f;
            if ((unsigned)yy < HH && (unsigned)xx < WW)
                v = __ldg(xb + c*HW + yy*WW + xx);
            As[k*68 + am] = v;
        }
        #pragma unroll
        for (int i = 0; i < 16; i++) {
            int o = bo0 + i*8;
            Bs[bk*132 + o] = __ldg(w + (size_t)o*KCONV + kb + bk);
        }
        __syncthreads();
        #pragma unroll
        for (int k = 0; k < 16; k++) {
            float4 a0 = *(const float4*)(As + k*68  + (ty<<2));
            float4 a1 = *(const float4*)(As + k*68  + (ty<<2) + 32);
            float4 b0 = *(const float4*)(Bs + k*132 + (tx<<2));
            float4 b1 = *(const float4*)(Bs + k*132 + (tx<<2) + 64);
            float ar[8] = {a0.x,a0.y,a0.z,a0.w,a1.x,a1.y,a1.z,a1.w};
            float br[8] = {b0.x,b0.y,b0.z,b0.w,b1.x,b1.y,b1.z,b1.w};
            #pragma unroll
            for (int r = 0; r < 8; r++)
                #pragma unroll
                for (int c = 0; c < 8; c++)
                    acc[r][c] = fmaf(ar[r], br[c], acc[r][c]);
        }
        __syncthreads();
    }

    // epilogue: h (NHWC) = silu(conv*scale + bias)
    #pragma unroll
    for (int c8 = 0; c8 < 8; c8++) {
        int n = (tx<<2) + (c8&3) + ((c8>>2)<<6);
        float inv = rsqrtf(bv[n] + EPSS);
        float sc  = bg[n]*inv;
        float bi  = bb[n] - bm[n]*sc;
        #pragma unroll
        for (int r8 = 0; r8 < 8; r8++) {
            int row = (ty<<2) + (r8&3) + ((r8>>2)<<5);
            float v = acc[r8][c8]*sc + bi;
            g_h[(size_t)(m0+row)*CM + n] = siluf(v);
        }
    }
}

// ---------------------------------------------------------------------------
// Kernel 2: depthwise 3x3 + bias -> LayerNorm over 128 channels -> exact GELU
// one block per pixel, one thread per channel
// ---------------------------------------------------------------------------
__global__ __launch_bounds__(128) void dw_ln_gelu(
    const float* __restrict__ wdw, const float* __restrict__ bdw,
    const float* __restrict__ lg,  const float* __restrict__ lb)
{
    const int pix = blockIdx.x;
    const int c   = threadIdx.x;
    const int img = pix / HW;
    const int p   = pix - img*HW;
    const int py  = p / WW;
    const int px  = p - py*WW;
    const float* hb = g_h + (size_t)img*HW*CM;

    float s = bdw[c];
    #pragma unroll
    for (int ky = 0; ky < 3; ky++) {
        int yy = py + ky - 1;
        if ((unsigned)yy >= HH) continue;
        #pragma unroll
        for (int kx = 0; kx < 3; kx++) {
            int xx = px + kx - 1;
            if ((unsigned)xx >= WW) continue;
            s = fmaf(hb[(size_t)(yy*WW + xx)*CM + c], wdw[c*9 + ky*3 + kx], s);
        }
    }
    // block reduction (128 threads = 4 warps) for mean / var
    float r1 = s, r2 = s*s;
    #pragma unroll
    for (int o = 16; o; o >>= 1) {
        r1 += __shfl_xor_sync(0xffffffffu, r1, o);
        r2 += __shfl_xor_sync(0xffffffffu, r2, o);
    }
    __shared__ float rb[8];
    int wi = c >> 5;
    if ((c & 31) == 0) { rb[wi] = r1; rb[4+wi] = r2; }
    __syncthreads();
    float sum = rb[0]+rb[1]+rb[2]+rb[3];
    float ssq = rb[4]+rb[5]+rb[6]+rb[7];
    float mu  = sum * (1.f/CM);
    float var = ssq * (1.f/CM) - mu*mu;
    float tn  = (s - mu) * rsqrtf(var + EPSS) * lg[c] + lb[c];
    float ge  = 0.5f * tn * (1.f + erff(tn * 0.70710678118654752f));
    g_t[(size_t)pix*CM + c] = ge;
}

// ---------------------------------------------------------------------------
// Kernel 3/4/6: generic GEMM, K=128, M tile 64, N tile 128, 8x8 microtile.
// B is [K x Nout] row-major, optionally split into two column blocks (B|B2).
// EPI 0: C = acc + bias           (value proj, NHWC)
// EPI 1: C = acc + bias(|bias2)   (offset+mask logits, Nout=108)
// EPI 2: out = resid + silu(bn(acc + eb))  written NCHW via smem transpose
// ---------------------------------------------------------------------------
template<int EPI>
__global__ __launch_bounds__(128) void gemm_k128(
    const float* __restrict__ A,
    const float* __restrict__ B, const float* __restrict__ B2,
    int N1, int Nout,
    const float* __restrict__ bias, const float* __restrict__ bias2,
    float* __restrict__ C,
    const float* __restrict__ eb,
    const float* __restrict__ bg, const float* __restrict__ bb,
    const float* __restrict__ bm, const float* __restrict__ bv,
    const float* __restrict__ resid)
{
    __shared__ __align__(16) float sm[(EPI == 2) ? 128*65 : (16*68 + 16*132)];
    float* As = sm;
    float* Bs = sm + 16*68;

    const int t  = threadIdx.x;
    const int m0 = blockIdx.x * 64;
    const int n0 = blockIdx.y * 128;

    const int ak  = t & 15;          // A: k fixed
    const int am0 = t >> 4;          // m = am0 + 8*i
    const int tx = t & 15, ty = t >> 4;

    float acc[8][8];
    #pragma unroll
    for (int r = 0; r < 8; r++)
        #pragma unroll
        for (int c = 0; c < 8; c++) acc[r][c] = 0.f;

    const int j = n0 + t;            // B: column fixed per thread
    for (int kb = 0; kb < 128; kb += 16) {
        #pragma unroll
        for (int i = 0; i < 8; i++) {
            int m = am0 + i*8;
            As[ak*68 + m] = A[(size_t)(m0+m)*128 + kb + ak];
        }
        #pragma unroll
        for (int i = 0; i < 16; i++) {
            float v = 0.f;
            if (j < N1)        v = B[(size_t)(kb+i)*N1 + j];
            else if (j < Nout) v = B2[(size_t)(kb+i)*(Nout-N1) + (j-N1)];
            Bs[i*132 + t] = v;
        }
        __syncthreads();
        #pragma unroll
        for (int k = 0; k < 16; k++) {
            float4 a0 = *(const float4*)(As + k*68  + (ty<<2));
            float4 a1 = *(const float4*)(As + k*68  + (ty<<2) + 32);
            float4 b0 = *(const float4*)(Bs + k*132 + (tx<<2));
            float4 b1 = *(const float4*)(Bs + k*132 + (tx<<2) + 64);
            float ar[8] = {a0.x,a0.y,a0.z,a0.w,a1.x,a1.y,a1.z,a1.w};
            float br[8] = {b0.x,b0.y,b0.z,b0.w,b1.x,b1.y,b1.z,b1.w};
            #pragma unroll
            for (int r = 0; r < 8; r++)
                #pragma unroll
                for (int c = 0; c < 8; c++)
                    acc[r][c] = fmaf(ar[r], br[c], acc[r][c]);
        }
        __syncthreads();
    }

    if (EPI != 2) {
        // per-column bias (split lookup)
        float bvs[8];
        #pragma unroll
        for (int c8 = 0; c8 < 8; c8++) {
            int jj = n0 + (tx<<2) + (c8&3) + ((c8>>2)<<6);
            float b = 0.f;
            if (jj < N1)        b = bias[jj];
            else if (jj < Nout) b = bias2[jj - N1];
            bvs[c8] = b;
        }
        #pragma unroll
        for (int r8 = 0; r8 < 8; r8++) {
            int row = (ty<<2) + (r8&3) + ((r8>>2)<<5);
            size_t base = (size_t)(m0+row)*Nout + n0;
            #pragma unroll
            for (int cH = 0; cH < 2; cH++) {
                int n = (tx<<2) + (cH<<6);
                if (n0 + n < Nout) {
                    float4 o;
                    o.x = acc[r8][cH*4+0] + bvs[cH*4+0];
                    o.y = acc[r8][cH*4+1] + bvs[cH*4+1];
                    o.z = acc[r8][cH*4+2] + bvs[cH*4+2];
                    o.w = acc[r8][cH*4+3] + bvs[cH*4+3];
                    *(float4*)(C + base + n) = o;
                }
            }
        }
    } else {
        // stage silu(bn(acc+bias)) transposed in smem, then coalesced NCHW write
        #pragma unroll
        for (int c8 = 0; c8 < 8; c8++) {
            int n  = (tx<<2) + (c8&3) + ((c8>>2)<<6);
            int co = n0 + n;
            float inv = rsqrtf(bv[co] + EPSS);
            float sc  = bg[co]*inv;
            float bi  = bb[co] - bm[co]*sc;
            float bo  = eb[co];
            #pragma unroll
            for (int r8 = 0; r8 < 8; r8++) {
                int row = (ty<<2) + (r8&3) + ((r8>>2)<<5);
                float v = (acc[r8][c8] + bo)*sc + bi;
                sm[n*65 + row] = siluf(v);
            }
        }
        __syncthreads();
        const int mloc = t & 63;
        const int nb0  = t >> 6;     // 0/1
        const int mg   = m0 + mloc;
        const int img  = mg / HW;
        const int pp   = mg - img*HW;
        const size_t obase = (size_t)img*C2*HW + pp;
        #pragma unroll
        for (int i = 0; i < 64; i++) {
            int n = nb0 + i*2;
            size_t adr = obase + (size_t)(n0 + n)*HW;
            C[adr] = resid[adr] + sm[n*65 + mloc];
        }
    }
}

// ---------------------------------------------------------------------------
// Kernel 5: DCNv3 core. One warp per (pixel, group); lane = channel in group.
// Softmax of the 9 mask logits computed in-register (lane-redundant).
// Padded-coordinate algebra: px = ix + (k/3) + dx ; py = iy + (k%3) + dy,
// padded value nonzero iff 1 <= coord <= 56  ->  value[coord-1].
// ---------------------------------------------------------------------------
__global__ __launch_bounds__(256) void dcn_core()
{
    int gw   = (blockIdx.x*blockDim.x + threadIdx.x) >> 5;
    int lane = threadIdx.x & 31;
    if (gw >= NPIX*GG) return;
    int pid = gw >> 2;
    int g   = gw & 3;
    int img = pid / HW;
    int p   = pid - img*HW;
    int iy  = p / WW;
    int ix  = p - iy*WW;

    const float* om = g_om + (size_t)pid*NOM;
    float m9[9]; float mx = -1e30f;
    #pragma unroll
    for (int k = 0; k < 9; k++) { m9[k] = om[72 + g*9 + k]; mx = fmaxf(mx, m9[k]); }
    float se = 0.f;
    #pragma unroll
    for (int k = 0; k < 9; k++) { m9[k] = expf(m9[k] - mx); se += m9[k]; }
    float inv = 1.f / se;

    const float* vb = g_v + (size_t)img*HW*CM + g*GC + lane;
    float acc = 0.f;
    #pragma unroll
    for (int k = 0; k < 9; k++) {
        float dx = om[(g*9 + k)*2];
        float dy = om[(g*9 + k)*2 + 1];
        int kxi = k / 3;
        int kyi = k - kxi*3;
        float fx = (float)(ix + kxi) + dx;   // padded x coord
        float fy = (float)(iy + kyi) + dy;   // padded y coord
        float x0f = floorf(fx), y0f = floorf(fy);
        float wx = fx - x0f, wy = fy - y0f;
        int x0 = (int)x0f, y0 = (int)y0f;
        int xm = x0 - 1, ym = y0 - 1;        // unpadded value coords
        float v00 = 0.f, v01 = 0.f, v10 = 0.f, v11 = 0.f;
        bool vx0 = (unsigned)xm     < WW;
        bool vx1 = (unsigned)(xm+1) < WW;
        bool vy0 = (unsigned)ym     < HH;
        bool vy1 = (unsigned)(ym+1) < HH;
        if (vy0 && vx0) v00 = vb[(size_t)(ym*WW + xm      )*CM];
        if (vy0 && vx1) v01 = vb[(size_t)(ym*WW + xm + 1  )*CM];
        if (vy1 && vx0) v10 = vb[(size_t)((ym+1)*WW + xm  )*CM];
        if (vy1 && vx1) v11 = vb[(size_t)((ym+1)*WW + xm+1)*CM];
        float sv = v00*(1.f-wy)*(1.f-wx) + v01*(1.f-wy)*wx
                 + v10*wy*(1.f-wx)       + v11*wy*wx;
        acc = fmaf(m9[k]*inv, sv, acc);
    }
    g_o[(size_t)pid*CM + g*GC + lane] = acc;
}

// ---------------------------------------------------------------------------
extern "C" void kernel_launch(void* const* d_in, const int* in_sizes, int n_in,
                              void* d_out, int out_size)
{
    const float* x    = (const float*)d_in[0];
    const float* wcv1 = (const float*)d_in[1];
    const float* bn1g = (const float*)d_in[2];
    const float* bn1b = (const float*)d_in[3];
    const float* bn1m = (const float*)d_in[4];
    const float* bn1v = (const float*)d_in[5];
    const float* wdw  = (const float*)d_in[6];
    const float* bdw  = (const float*)d_in[7];
    const float* lng  = (const float*)d_in[8];
    const float* lnb  = (const float*)d_in[9];
    const float* winp = (const float*)d_in[10];
    const float* binp = (const float*)d_in[11];
    const float* woff = (const float*)d_in[12];
    const float* boff = (const float*)d_in[13];
    const float* wmsk = (const float*)d_in[14];
    const float* bmsk = (const float*)d_in[15];
    const float* wout = (const float*)d_in[16];
    const float* bout = (const float*)d_in[17];
    const float* bn2g = (const float*)d_in[18];
    const float* bn2b = (const float*)d_in[19];
    const float* bn2m = (const float*)d_in[20];
    const float* bn2v = (const float*)d_in[21];
    float* out = (float*)d_out;

    float *ph, *pt, *pv, *pom, *po;
    cudaGetSymbolAddress((void**)&ph,  g_h);
    cudaGetSymbolAddress((void**)&pt,  g_t);
    cudaGetSymbolAddress((void**)&pv,  g_v);
    cudaGetSymbolAddress((void**)&pom, g_om);
    cudaGetSymbolAddress((void**)&po,  g_o);

    // 1) conv1 + BN + SiLU -> g_h (NHWC)
    conv1_bn_silu<<<NPIX/64, 128>>>(x, wcv1, bn1g, bn1b, bn1m, bn1v);
    // 2) depthwise + LN + GELU -> g_t (NHWC)
    dw_ln_gelu<<<NPIX, 128>>>(wdw, bdw, lng, lnb);
    // 3) value projection -> g_v
    gemm_k128<0><<<dim3(NPIX/64, 1), 128>>>(ph, winp, nullptr, CM, CM,
        binp, nullptr, pv, nullptr, nullptr, nullptr, nullptr, nullptr, nullptr);
    // 4) offsets + mask logits -> g_om (Nout=108)
    gemm_k128<1><<<dim3(NPIX/64, 1), 128>>>(pt, woff, wmsk, 72, NOM,
        boff, bmsk, pom, nullptr, nullptr, nullptr, nullptr, nullptr, nullptr);
    // 5) deformable sampling -> g_o
    dcn_core<<<(NPIX*GG)/8, 256>>>();
    // 6) output projection + BN + SiLU + residual -> out (NCHW)
    gemm_k128<2><<<dim3(NPIX/64, 2), 128>>>(po, wout, nullptr, C2, C2,
        nullptr, nullptr, out, bout, bn2g, bn2b, bn2m, bn2v, x);
}